// round 15
// baseline (speedup 1.0000x reference)
#include <cuda_runtime.h>

// 5x5 box-filter mean, reflect padding, NCHW fp32, H=W=512.
// R15 = R13 body (128-thr CTAs, 4 out rows / 8 in rows per thread, vertical
// tree partials, deferred halo, shuffle horizontal, 48-reg cap) looped over
// 8 z-planes per CTA: grid 1536 ~= 1 wave at 10 CTAs/SM. Kills ~8 waves of
// scheduling/transition overhead; independent iterations let the scoreboard
// overlap next-plane loads with current-plane tail.

#define IMG 512
#define TW  128   // tile width  (floats) = 32 lanes * 4
#define TH  16    // tile height (rows)   = 4 warps * 4
#define ZPC 8     // planes per CTA

__device__ __forceinline__ int refl(int x) {
    return (x < 0) ? -x : ((x >= IMG) ? (2 * IMG - 2 - x) : x);
}

__global__ __launch_bounds__(128, 10)
void box5_kernel(const float* __restrict__ in, float* __restrict__ out)
{
    const int lane = threadIdx.x;       // 0..31 -> float4 column
    const int wrp  = threadIdx.y;       // 0..3  -> 4-row group

    const int tile_x = blockIdx.x * TW;
    const int tile_y = blockIdx.y * TH;

    const int colx  = tile_x + lane * 4;
    const int rbase = tile_y + wrp * 4 - 2;   // first of 8 input rows
    const bool interior_y = (rbase >= 0) && (rbase + 7 < IMG);

    const size_t plane0 = (size_t)(blockIdx.z * ZPC) * (IMG * IMG);
    const float* __restrict__ img0  = in  + plane0;
    float* __restrict__       oimg0 = out + plane0;

    for (int z = 0; z < ZPC; z++) {
        const float* __restrict__ img  = img0  + (size_t)z * (IMG * IMG);
        float* __restrict__       oimg = oimg0 + (size_t)z * (IMG * IMG);

        // ---- Front-batched loads: 8 rows x LDG.128 ----
        float4 c[8];
        if (interior_y) {
            const float* p = img + rbase * IMG + colx;
            #pragma unroll
            for (int k = 0; k < 8; k++)
                c[k] = *reinterpret_cast<const float4*>(p + k * IMG);  // imm offsets
        } else {
            #pragma unroll
            for (int k = 0; k < 8; k++)
                c[k] = *reinterpret_cast<const float4*>(img + refl(rbase + k) * IMG + colx);
        }

        // ---- Vertical 5-sums via tree partials (c[] dies here) ----
        float4 a, b, d;
        a.x = c[1].x + c[2].x;  a.y = c[1].y + c[2].y;  a.z = c[1].z + c[2].z;  a.w = c[1].w + c[2].w;
        b.x = c[3].x + c[4].x;  b.y = c[3].y + c[4].y;  b.z = c[3].z + c[4].z;  b.w = c[3].w + c[4].w;
        d.x = c[5].x + c[6].x;  d.y = c[5].y + c[6].y;  d.z = c[5].z + c[6].z;  d.w = c[5].w + c[6].w;

        float4 v[4];
        v[0].x = c[0].x + a.x + b.x;  v[0].y = c[0].y + a.y + b.y;
        v[0].z = c[0].z + a.z + b.z;  v[0].w = c[0].w + a.w + b.w;
        v[1].x = a.x + b.x + c[5].x;  v[1].y = a.y + b.y + c[5].y;
        v[1].z = a.z + b.z + c[5].z;  v[1].w = a.w + b.w + c[5].w;
        v[2].x = c[2].x + b.x + d.x;  v[2].y = c[2].y + b.y + d.y;
        v[2].z = c[2].z + b.z + d.z;  v[2].w = c[2].w + b.w + d.w;
        v[3].x = b.x + d.x + c[7].x;  v[3].y = b.y + d.y + c[7].y;
        v[3].z = b.z + d.z + c[7].z;  v[3].w = b.w + d.w + c[7].w;

        // ---- Deferred x-halo (L1 hits) for lanes 0/31, then vertical tree ----
        float2 ve[4] = {};
        if (lane == 0 || lane == 31) {
            const bool left = (lane == 0);
            float2 e[8];
            if (left) {
                if (tile_x == 0) {
                    #pragma unroll
                    for (int k = 0; k < 8; k++) {          // reflect: -2 -> 2, -1 -> 1
                        const float* rp = img + refl(rbase + k) * IMG;
                        e[k].x = rp[2];
                        e[k].y = rp[1];
                    }
                } else if (interior_y) {
                    const float* p = img + rbase * IMG + tile_x - 2;
                    #pragma unroll
                    for (int k = 0; k < 8; k++)
                        e[k] = *reinterpret_cast<const float2*>(p + k * IMG);
                } else {
                    #pragma unroll
                    for (int k = 0; k < 8; k++)
                        e[k] = *reinterpret_cast<const float2*>(
                            img + refl(rbase + k) * IMG + tile_x - 2);
                }
            } else {
                if (tile_x + TW == IMG) {
                    #pragma unroll
                    for (int k = 0; k < 8; k++) {          // reflect: 512 -> 510, 513 -> 509
                        const float* rp = img + refl(rbase + k) * IMG;
                        e[k].x = rp[IMG - 2];
                        e[k].y = rp[IMG - 3];
                    }
                } else if (interior_y) {
                    const float* p = img + rbase * IMG + tile_x + TW;
                    #pragma unroll
                    for (int k = 0; k < 8; k++)
                        e[k] = *reinterpret_cast<const float2*>(p + k * IMG);
                } else {
                    #pragma unroll
                    for (int k = 0; k < 8; k++)
                        e[k] = *reinterpret_cast<const float2*>(
                            img + refl(rbase + k) * IMG + tile_x + TW);
                }
            }
            float2 ae, be, de;
            ae.x = e[1].x + e[2].x;  ae.y = e[1].y + e[2].y;
            be.x = e[3].x + e[4].x;  be.y = e[3].y + e[4].y;
            de.x = e[5].x + e[6].x;  de.y = e[5].y + e[6].y;
            ve[0].x = e[0].x + ae.x + be.x;  ve[0].y = e[0].y + ae.y + be.y;
            ve[1].x = ae.x + be.x + e[5].x;  ve[1].y = ae.y + be.y + e[5].y;
            ve[2].x = e[2].x + be.x + de.x;  ve[2].y = e[2].y + be.y + de.y;
            ve[3].x = be.x + de.x + e[7].x;  ve[3].y = be.y + de.y + e[7].y;
        }

        // ---- Horizontal 5-tap on summed rows (4 shuffles/row) + store ----
        const float inv25 = 1.0f / 25.0f;
        float* obase = oimg + (tile_y + wrp * 4) * IMG + colx;

        #pragma unroll
        for (int r = 0; r < 4; r++) {
            float pz = __shfl_up_sync(0xffffffffu, v[r].z, 1);   // col -2
            float pw = __shfl_up_sync(0xffffffffu, v[r].w, 1);   // col -1
            float nx = __shfl_down_sync(0xffffffffu, v[r].x, 1); // col +4
            float ny = __shfl_down_sync(0xffffffffu, v[r].y, 1); // col +5
            if (lane == 0)  { pz = ve[r].x; pw = ve[r].y; }
            if (lane == 31) { nx = ve[r].x; ny = ve[r].y; }

            const float s = v[r].x + v[r].y + v[r].z + v[r].w;
            float4 o;
            o.x = ((s - v[r].w) + pz + pw) * inv25;   // cols -2..2
            o.y = (s + pw) * inv25;                   // cols -1..3
            o.z = (s + nx) * inv25;                   // cols  0..4
            o.w = ((s - v[r].x) + nx + ny) * inv25;   // cols  1..5
            *reinterpret_cast<float4*>(obase + r * IMG) = o;
        }
    }
}

extern "C" void kernel_launch(void* const* d_in, const int* in_sizes, int n_in,
                              void* d_out, int out_size)
{
    const float* in = (const float*)d_in[0];
    float* out = (float*)d_out;

    const int planes = in_sizes[0] / (IMG * IMG);   // 96

    dim3 grid(IMG / TW, IMG / TH, planes / ZPC);    // (4, 32, 12) = 1536
    dim3 block(32, 4);
    box5_kernel<<<grid, block>>>(in, out);
}

// round 16
// speedup vs baseline: 1.5231x; 1.5231x over previous
#include <cuda_runtime.h>

// 5x5 box-filter mean, reflect padding, NCHW fp32, H=W=512.
// R16: two-phase sliding window -> 8 output rows from 12 input rows per
// thread (vertical read amplification 1.5x vs 2.0x), cutting L2 read traffic
// ~25%. Phase layout overlaps phase-2 loads with phase-1 shuffle/store tail.
// 128-thr CTAs, vertical tree partials, deferred halo, shuffle horizontal.

#define IMG 512
#define TW  128   // tile width  (floats) = 32 lanes * 4
#define TH  32    // tile height (rows)   = 4 warps * 8

__device__ __forceinline__ int refl(int x) {
    return (x < 0) ? -x : ((x >= IMG) ? (2 * IMG - 2 - x) : x);
}

// vertical 5-sum tree over an 8-row window w[0..7] -> 4 rows
__device__ __forceinline__ void vsum8(const float4* w, float4* v)
{
    float4 a, b, d;
    a.x = w[1].x + w[2].x;  a.y = w[1].y + w[2].y;  a.z = w[1].z + w[2].z;  a.w = w[1].w + w[2].w;
    b.x = w[3].x + w[4].x;  b.y = w[3].y + w[4].y;  b.z = w[3].z + w[4].z;  b.w = w[3].w + w[4].w;
    d.x = w[5].x + w[6].x;  d.y = w[5].y + w[6].y;  d.z = w[5].z + w[6].z;  d.w = w[5].w + w[6].w;
    v[0].x = w[0].x + a.x + b.x;  v[0].y = w[0].y + a.y + b.y;
    v[0].z = w[0].z + a.z + b.z;  v[0].w = w[0].w + a.w + b.w;
    v[1].x = a.x + b.x + w[5].x;  v[1].y = a.y + b.y + w[5].y;
    v[1].z = a.z + b.z + w[5].z;  v[1].w = a.w + b.w + w[5].w;
    v[2].x = w[2].x + b.x + d.x;  v[2].y = w[2].y + b.y + d.y;
    v[2].z = w[2].z + b.z + d.z;  v[2].w = w[2].w + b.w + d.w;
    v[3].x = b.x + d.x + w[7].x;  v[3].y = b.y + d.y + w[7].y;
    v[3].z = b.z + d.z + w[7].z;  v[3].w = b.w + d.w + w[7].w;
}

// halo loads (lanes 0/31) for an 8-row window starting at wbase, then tree
__device__ __forceinline__ void halo8(const float* __restrict__ img,
                                      int wbase, int tile_x, bool interior,
                                      int lane, float2* ve)
{
    #pragma unroll
    for (int k = 0; k < 4; k++) { ve[k].x = 0.f; ve[k].y = 0.f; }
    if (lane == 0 || lane == 31) {
        const bool left = (lane == 0);
        float2 e[8];
        if (left) {
            if (tile_x == 0) {
                #pragma unroll
                for (int k = 0; k < 8; k++) {          // reflect: -2 -> 2, -1 -> 1
                    const float* rp = img + refl(wbase + k) * IMG;
                    e[k].x = rp[2];
                    e[k].y = rp[1];
                }
            } else if (interior) {
                const float* p = img + wbase * IMG + tile_x - 2;
                #pragma unroll
                for (int k = 0; k < 8; k++)
                    e[k] = *reinterpret_cast<const float2*>(p + k * IMG);
            } else {
                #pragma unroll
                for (int k = 0; k < 8; k++)
                    e[k] = *reinterpret_cast<const float2*>(
                        img + refl(wbase + k) * IMG + tile_x - 2);
            }
        } else {
            if (tile_x + TW == IMG) {
                #pragma unroll
                for (int k = 0; k < 8; k++) {          // reflect: 512 -> 510, 513 -> 509
                    const float* rp = img + refl(wbase + k) * IMG;
                    e[k].x = rp[IMG - 2];
                    e[k].y = rp[IMG - 3];
                }
            } else if (interior) {
                const float* p = img + wbase * IMG + tile_x + TW;
                #pragma unroll
                for (int k = 0; k < 8; k++)
                    e[k] = *reinterpret_cast<const float2*>(p + k * IMG);
            } else {
                #pragma unroll
                for (int k = 0; k < 8; k++)
                    e[k] = *reinterpret_cast<const float2*>(
                        img + refl(wbase + k) * IMG + tile_x + TW);
            }
        }
        float2 ae, be, de;
        ae.x = e[1].x + e[2].x;  ae.y = e[1].y + e[2].y;
        be.x = e[3].x + e[4].x;  be.y = e[3].y + e[4].y;
        de.x = e[5].x + e[6].x;  de.y = e[5].y + e[6].y;
        ve[0].x = e[0].x + ae.x + be.x;  ve[0].y = e[0].y + ae.y + be.y;
        ve[1].x = ae.x + be.x + e[5].x;  ve[1].y = ae.y + be.y + e[5].y;
        ve[2].x = e[2].x + be.x + de.x;  ve[2].y = e[2].y + be.y + de.y;
        ve[3].x = be.x + de.x + e[7].x;  ve[3].y = be.y + de.y + e[7].y;
    }
}

__device__ __forceinline__ void shuffle_store4(const float4* v, const float2* ve,
                                               float* obase, int lane)
{
    const float inv25 = 1.0f / 25.0f;
    #pragma unroll
    for (int r = 0; r < 4; r++) {
        float pz = __shfl_up_sync(0xffffffffu, v[r].z, 1);   // col -2
        float pw = __shfl_up_sync(0xffffffffu, v[r].w, 1);   // col -1
        float nx = __shfl_down_sync(0xffffffffu, v[r].x, 1); // col +4
        float ny = __shfl_down_sync(0xffffffffu, v[r].y, 1); // col +5
        float vz = v[r].z, vw = v[r].w, vx = v[r].x, vy = v[r].y;
        if (lane == 0)  { pz = ve[r].x; pw = ve[r].y; }
        if (lane == 31) { nx = ve[r].x; ny = ve[r].y; }

        const float s = vx + vy + vz + vw;
        float4 o;
        o.x = ((s - vw) + pz + pw) * inv25;   // cols -2..2
        o.y = (s + pw) * inv25;               // cols -1..3
        o.z = (s + nx) * inv25;               // cols  0..4
        o.w = ((s - vx) + nx + ny) * inv25;   // cols  1..5
        *reinterpret_cast<float4*>(obase + r * IMG) = o;
    }
}

__global__ __launch_bounds__(128)
void box5_kernel(const float* __restrict__ in, float* __restrict__ out)
{
    const int lane = threadIdx.x;       // 0..31 -> float4 column
    const int wrp  = threadIdx.y;       // 0..3  -> 8-row group

    const int tile_x = blockIdx.x * TW;
    const int tile_y = blockIdx.y * TH;
    const float* __restrict__ img  = in  + (size_t)blockIdx.z * (IMG * IMG);
    float* __restrict__       oimg = out + (size_t)blockIdx.z * (IMG * IMG);

    const int colx  = tile_x + lane * 4;
    const int rbase = tile_y + wrp * 8 - 2;   // first of 12 input rows
    const bool interior_y = (rbase >= 0) && (rbase + 11 < IMG);

    float* obase = oimg + (tile_y + wrp * 8) * IMG + colx;

    // ---- Phase 1: load rows 0..7 ----
    float4 c[12];
    if (interior_y) {
        const float* p = img + rbase * IMG + colx;
        #pragma unroll
        for (int k = 0; k < 8; k++)
            c[k] = *reinterpret_cast<const float4*>(p + k * IMG);
    } else {
        #pragma unroll
        for (int k = 0; k < 8; k++)
            c[k] = *reinterpret_cast<const float4*>(img + refl(rbase + k) * IMG + colx);
    }

    // vsum rows 0..3 (c0..c3 die)
    float4 v[4];
    vsum8(&c[0], v);

    // ---- Phase 2 loads issued here (rows 8..11), in flight during tail ----
    if (interior_y) {
        const float* p = img + (rbase + 8) * IMG + colx;
        #pragma unroll
        for (int k = 0; k < 4; k++)
            c[8 + k] = *reinterpret_cast<const float4*>(p + k * IMG);
    } else {
        #pragma unroll
        for (int k = 0; k < 4; k++)
            c[8 + k] = *reinterpret_cast<const float4*>(img + refl(rbase + 8 + k) * IMG + colx);
    }

    // ---- Phase 1 tail: halo (L1 hits), shuffles, stores rows 0..3 ----
    float2 ve[4];
    halo8(img, rbase, tile_x, interior_y, lane, ve);
    shuffle_store4(v, ve, obase, lane);

    // ---- Phase 2: vsum rows 4..7 on window c[4..11], halo, store ----
    vsum8(&c[4], v);
    halo8(img, rbase + 4, tile_x, interior_y, lane, ve);
    shuffle_store4(v, ve, obase + 4 * IMG, lane);
}

extern "C" void kernel_launch(void* const* d_in, const int* in_sizes, int n_in,
                              void* d_out, int out_size)
{
    const float* in = (const float*)d_in[0];
    float* out = (float*)d_out;

    const int planes = in_sizes[0] / (IMG * IMG);   // 96

    dim3 grid(IMG / TW, IMG / TH, planes);          // (4, 16, 96) = 6144
    dim3 block(32, 4);
    box5_kernel<<<grid, block>>>(in, out);
}